// round 1
// baseline (speedup 1.0000x reference)
#include <cuda_runtime.h>
#include <cuda_bf16.h>
#include <cstdint>

// ---------------------------------------------------------------------------
// Problem shapes (fixed by the dataset)
// ---------------------------------------------------------------------------
#define MB   4096   // batch
#define DIN  512
#define HID  2048
// scores: [MB, 1]; rank over the batch (n = MB)

// Scratch (device globals: allocation inside kernel_launch is forbidden)
__device__ float g_h1[(size_t)MB * HID];
__device__ float g_h2[(size_t)MB * HID];
__device__ float g_scores[MB];

// ---------------------------------------------------------------------------
// SGEMM: C[M,N] = relu?(A[M,K] @ B[K,N] + bias[N])
// 128x128 block tile, 8-deep K tile, 8x8 per-thread micro-tile, 256 threads.
// M % 128 == 0, N % 128 == 0, K % 8 == 0 (true for all three layers).
// ---------------------------------------------------------------------------
#define BM 128
#define BN 128
#define BK 8
#define TM 8
#define TN 8

__global__ __launch_bounds__(256, 2)
void sgemm_bias_relu(int M, int N, int K,
                     const float* __restrict__ A,
                     const float* __restrict__ B,
                     const float* __restrict__ bias,
                     float* __restrict__ C,
                     int do_relu)
{
    __shared__ float As[BK][BM];
    __shared__ float Bs[BK][BN];

    const int tid  = threadIdx.x;
    const int brow = blockIdx.y;
    const int bcol = blockIdx.x;

    const float* Ab = A + (size_t)brow * BM * K;
    const float* Bb = B + (size_t)bcol * BN;
    float*       Cb = C + (size_t)brow * BM * N + (size_t)bcol * BN;
    const float* bb = bias + (size_t)bcol * BN;

    const int aRow = tid >> 1;          // 0..127
    const int aCol = (tid & 1) * 4;     // 0 or 4
    const int bRow = tid >> 5;          // 0..7
    const int bCol = (tid & 31) * 4;    // 0..124

    const int tRow = (tid >> 4) * TM;   // 0..120
    const int tCol = (tid & 15) * TN;   // 0..120

    float acc[TM][TN];
    #pragma unroll
    for (int m = 0; m < TM; m++)
        #pragma unroll
        for (int n = 0; n < TN; n++)
            acc[m][n] = 0.0f;

    float regM[TM], regN[TN];

    for (int k0 = 0; k0 < K; k0 += BK) {
        // load A tile (transpose into As for conflict-free column reads)
        float4 a4 = *(const float4*)(Ab + (size_t)aRow * K + k0 + aCol);
        As[aCol + 0][aRow] = a4.x;
        As[aCol + 1][aRow] = a4.y;
        As[aCol + 2][aRow] = a4.z;
        As[aCol + 3][aRow] = a4.w;
        // load B tile
        float4 b4 = *(const float4*)(Bb + (size_t)(k0 + bRow) * N + bCol);
        *(float4*)&Bs[bRow][bCol] = b4;
        __syncthreads();

        #pragma unroll
        for (int k = 0; k < BK; k++) {
            #pragma unroll
            for (int m = 0; m < TM; m++) regM[m] = As[k][tRow + m];
            #pragma unroll
            for (int n = 0; n < TN; n++) regN[n] = Bs[k][tCol + n];
            #pragma unroll
            for (int m = 0; m < TM; m++)
                #pragma unroll
                for (int n = 0; n < TN; n++)
                    acc[m][n] = fmaf(regM[m], regN[n], acc[m][n]);
        }
        __syncthreads();
    }

    // epilogue: bias + optional relu, vectorized stores
    #pragma unroll
    for (int m = 0; m < TM; m++) {
        const int row = tRow + m;
        #pragma unroll
        for (int n = 0; n < TN; n += 4) {
            float4 v;
            v.x = acc[m][n + 0] + bb[tCol + n + 0];
            v.y = acc[m][n + 1] + bb[tCol + n + 1];
            v.z = acc[m][n + 2] + bb[tCol + n + 2];
            v.w = acc[m][n + 3] + bb[tCol + n + 3];
            if (do_relu) {
                v.x = fmaxf(v.x, 0.0f);
                v.y = fmaxf(v.y, 0.0f);
                v.z = fmaxf(v.z, 0.0f);
                v.w = fmaxf(v.w, 0.0f);
            }
            *(float4*)(Cb + (size_t)row * N + tCol + n) = v;
        }
    }
}

// ---------------------------------------------------------------------------
// GEMV: scores[r] = dot(H[r, :K], w) + b   (warp per row, float4 loads)
// ---------------------------------------------------------------------------
__global__ __launch_bounds__(256)
void gemv_scores(const float* __restrict__ H,
                 const float* __restrict__ w,
                 const float* __restrict__ b3,
                 float* __restrict__ scores,
                 int rows, int K)
{
    const int gwarp = (blockIdx.x * blockDim.x + threadIdx.x) >> 5;
    const int lane  = threadIdx.x & 31;
    if (gwarp >= rows) return;

    const float4* r4 = (const float4*)(H + (size_t)gwarp * K);
    const float4* w4 = (const float4*)w;
    const int K4 = K >> 2;  // 512 for K=2048

    float acc = 0.0f;
    for (int t = lane; t < K4; t += 32) {
        float4 a = r4[t];
        float4 b = w4[t];
        acc += a.x * b.x + a.y * b.y + a.z * b.z + a.w * b.w;
    }
    #pragma unroll
    for (int o = 16; o > 0; o >>= 1)
        acc += __shfl_down_sync(0xffffffffu, acc, o);
    if (lane == 0) scores[gwarp] = acc + b3[0];
}

// ---------------------------------------------------------------------------
// soft_rank over n=4096 scores, single block of 1024 threads.
//   1. bitonic sort descending in shared (keys + original indices)
//   2. PAV (nonincreasing isotonic) on y = s - [n, n-1, ..., 1]  (thread 0,
//      stack top in registers, double sums for exact pooling decisions)
//   3. primal = s - dual, scatter to original order -> out[0..n)
//   4. copy scores -> out[n..2n)
// ---------------------------------------------------------------------------
__global__ void softrank_kernel(const float* __restrict__ scores,
                                float* __restrict__ out,
                                int n)
{
    extern __shared__ double dyn[];
    double* bsum  = dyn;                      // n doubles (block sums stack)
    float*  s     = (float*)(bsum + n);       // n
    float*  dual  = s + n;                    // n
    int*    idx   = (int*)(dual + n);         // n
    int*    bst   = idx + n;                  // n (block start stack)
    int*    bcn   = bst + n;                  // n (block count stack)

    const int tid = threadIdx.x;
    const int nt  = blockDim.x;

    for (int i = tid; i < n; i += nt) { s[i] = scores[i]; idx[i] = i; }
    __syncthreads();

    // bitonic sort, descending
    for (int k = 2; k <= n; k <<= 1) {
        for (int j = k >> 1; j > 0; j >>= 1) {
            for (int i = tid; i < n; i += nt) {
                int ixj = i ^ j;
                if (ixj > i) {
                    bool up = ((i & k) == 0);       // descending in "up" region
                    float a = s[i], b = s[ixj];
                    bool sw = up ? (a < b) : (a > b);
                    if (sw) {
                        s[i] = b; s[ixj] = a;
                        int t = idx[i]; idx[i] = idx[ixj]; idx[ixj] = t;
                    }
                }
            }
            __syncthreads();
        }
    }

    if (tid == 0) {
        // PAV for nonincreasing fit of y[i] = s[i] - (n - i)
        int top = -1;
        double cur_sum = (double)s[0] - (double)n;
        int cur_cnt = 1, cur_start = 0;

        for (int i = 1; i < n; i++) {
            double nsum = (double)s[i] - (double)(n - i);
            int ncnt = 1, nstart = i;
            // violation: mean(cur) < mean(new)  => merge
            while (cur_cnt > 0 &&
                   cur_sum * (double)ncnt < nsum * (double)cur_cnt) {
                nsum += cur_sum; ncnt += cur_cnt; nstart = cur_start;
                if (top >= 0) {
                    cur_sum = bsum[top]; cur_cnt = bcn[top]; cur_start = bst[top];
                    top--;
                } else {
                    cur_cnt = 0;
                }
            }
            if (cur_cnt > 0) {
                top++;
                bsum[top] = cur_sum; bcn[top] = cur_cnt; bst[top] = cur_start;
            }
            cur_sum = nsum; cur_cnt = ncnt; cur_start = nstart;
        }
        top++;
        bsum[top] = cur_sum; bcn[top] = cur_cnt; bst[top] = cur_start;

        // expand block means into dual[]
        for (int b = 0; b <= top; b++) {
            float mean = (float)(bsum[b] / (double)bcn[b]);
            int st = bst[b], en = st + bcn[b];
            for (int t = st; t < en; t++) dual[t] = mean;
        }
    }
    __syncthreads();

    for (int i = tid; i < n; i += nt) {
        out[idx[i]] = s[i] - dual[i];   // rank in original order
        out[n + i]  = scores[i];        // scores passthrough
    }
}

// ---------------------------------------------------------------------------
// Launch
// ---------------------------------------------------------------------------
extern "C" void kernel_launch(void* const* d_in, const int* in_sizes, int n_in,
                              void* d_out, int out_size)
{
    const float* x  = (const float*)d_in[0];
    const float* W1 = (const float*)d_in[1];
    const float* b1 = (const float*)d_in[2];
    const float* W2 = (const float*)d_in[3];
    const float* b2 = (const float*)d_in[4];
    const float* W3 = (const float*)d_in[5];
    const float* b3 = (const float*)d_in[6];
    float* out = (float*)d_out;

    float *h1, *h2, *sc;
    cudaGetSymbolAddress((void**)&h1, g_h1);
    cudaGetSymbolAddress((void**)&h2, g_h2);
    cudaGetSymbolAddress((void**)&sc, g_scores);

    dim3 blk(256);

    // layer 1: [4096,512] @ [512,2048] + b1, relu
    {
        dim3 grid(HID / BN, MB / BM);
        sgemm_bias_relu<<<grid, blk>>>(MB, HID, DIN, x, W1, b1, h1, 1);
    }
    // layer 2: [4096,2048] @ [2048,2048] + b2, relu
    {
        dim3 grid(HID / BN, MB / BM);
        sgemm_bias_relu<<<grid, blk>>>(MB, HID, HID, h1, W2, b2, h2, 1);
    }
    // layer 3 (GEMV): scores = h2 @ W3 + b3
    {
        int warps_per_block = 256 / 32;
        int blocks = (MB + warps_per_block - 1) / warps_per_block;
        gemv_scores<<<blocks, 256>>>(h2, W3, b3, sc, MB, HID);
    }
    // soft_rank + output assembly
    {
        size_t smem = (size_t)MB * sizeof(double)      // bsum
                    + (size_t)MB * sizeof(float) * 2   // s, dual
                    + (size_t)MB * sizeof(int) * 3;    // idx, bst, bcn
        cudaFuncSetAttribute(softrank_kernel,
                             cudaFuncAttributeMaxDynamicSharedMemorySize,
                             (int)smem);
        softrank_kernel<<<1, 1024, smem>>>(sc, out, MB);
    }
}

// round 3
// speedup vs baseline: 1.3998x; 1.3998x over previous
#include <cuda_runtime.h>
#include <cuda_bf16.h>
#include <cstdint>

// ---------------------------------------------------------------------------
// Shapes (fixed by the dataset)
// ---------------------------------------------------------------------------
#define MB   4096
#define DIN  512
#define HID  2048

// ---------------------------------------------------------------------------
// Device scratch
// ---------------------------------------------------------------------------
__device__ __nv_bfloat16 g_xhi[(size_t)MB * DIN],  g_xlo[(size_t)MB * DIN];
__device__ __nv_bfloat16 g_w1hi[(size_t)HID * DIN], g_w1lo[(size_t)HID * DIN];
__device__ __nv_bfloat16 g_w2hi[(size_t)HID * HID], g_w2lo[(size_t)HID * HID];
__device__ __nv_bfloat16 g_h1hi[(size_t)MB * HID],  g_h1lo[(size_t)MB * HID];
__device__ float g_h2[(size_t)MB * HID];
__device__ float g_scores[MB];

// ---------------------------------------------------------------------------
// Helpers
// ---------------------------------------------------------------------------
__device__ __forceinline__ uint32_t smem_u32(const void* p) {
    uint32_t a;
    asm("{ .reg .u64 t; cvta.to.shared.u64 t, %1; cvt.u32.u64 %0, t; }"
        : "=r"(a) : "l"(p));
    return a;
}

#define SW128(o) ((o) ^ (((o) >> 3) & 0x70))

#define CPA16(smem, gptr) \
    asm volatile("cp.async.cg.shared.global [%0], [%1], 16;" \
                 :: "r"(smem), "l"(gptr))

#define LDMX4(r0, r1, r2, r3, addr) \
    asm volatile("ldmatrix.sync.aligned.m8n8.x4.shared.b16 {%0,%1,%2,%3}, [%4];" \
                 : "=r"(r0), "=r"(r1), "=r"(r2), "=r"(r3) : "r"(addr))

#define MMA16816(c, a, b) \
    asm volatile("mma.sync.aligned.m16n8k16.row.col.f32.bf16.bf16.f32 " \
                 "{%0,%1,%2,%3}, {%4,%5,%6,%7}, {%8,%9}, {%0,%1,%2,%3};" \
                 : "+f"((c)[0]), "+f"((c)[1]), "+f"((c)[2]), "+f"((c)[3]) \
                 : "r"((a)[0]), "r"((a)[1]), "r"((a)[2]), "r"((a)[3]), \
                   "r"((b)[0]), "r"((b)[1]))

// ---------------------------------------------------------------------------
// Conversion kernels: fp32 -> (bf16 hi, bf16 lo)
// ---------------------------------------------------------------------------
__global__ void split_rows(const float* __restrict__ in,
                           __nv_bfloat16* __restrict__ hi,
                           __nv_bfloat16* __restrict__ lo, int n)
{
    int i = (blockIdx.x * blockDim.x + threadIdx.x) * 4;
    if (i >= n) return;
    float4 v = *(const float4*)(in + i);
    float vv[4] = {v.x, v.y, v.z, v.w};
    #pragma unroll
    for (int k = 0; k < 4; k++) {
        __nv_bfloat16 h = __float2bfloat16(vv[k]);
        hi[i + k] = h;
        lo[i + k] = __float2bfloat16(vv[k] - __bfloat162float(h));
    }
}

// W [K,N] row-major -> T hi/lo [N,K]
__global__ void transpose_split(const float* __restrict__ W,
                                __nv_bfloat16* __restrict__ Thi,
                                __nv_bfloat16* __restrict__ Tlo,
                                int K, int N)
{
    __shared__ float t[32][33];
    int n0 = blockIdx.x * 32, k0 = blockIdx.y * 32;
    int tx = threadIdx.x, ty = threadIdx.y;
    #pragma unroll
    for (int r = ty; r < 32; r += 8)
        t[r][tx] = W[(size_t)(k0 + r) * N + n0 + tx];
    __syncthreads();
    #pragma unroll
    for (int r = ty; r < 32; r += 8) {
        float v = t[tx][r];
        __nv_bfloat16 h = __float2bfloat16(v);
        __nv_bfloat16 l = __float2bfloat16(v - __bfloat162float(h));
        size_t o = (size_t)(n0 + r) * K + k0 + tx;
        Thi[o] = h;
        Tlo[o] = l;
    }
}

// ---------------------------------------------------------------------------
// mma.sync GEMM: D[M,N] = relu(A @ B^T + bias), split-bf16 operands.
// A hi/lo [M,K] K-major; B hi/lo [N,K] K-major. CTA 128x128, KC=64, 8 warps,
// warp tile 64x32 (2x4 warp grid), m16n8k16 bf16 HMMA, fp32 accum.
// mode=1: write split bf16 (outHi/outLo); mode=0: write fp32 (outF).
// ---------------------------------------------------------------------------
#define BM 128
#define BN 128
#define KC 64                 // 64 bf16 = 128 bytes per row
#define TILE_BYTES 16384      // 128 rows * 128 B
#define S_A_HI 0
#define S_A_LO 16384
#define S_B_HI 32768
#define S_B_LO 49152
#define STAGE_BYTES 65536
#define GEMM_SMEM (2 * STAGE_BYTES)

__global__ __launch_bounds__(256, 1)
void gemm_mma(const __nv_bfloat16* __restrict__ Ahi,
              const __nv_bfloat16* __restrict__ Alo,
              const __nv_bfloat16* __restrict__ Bhi,
              const __nv_bfloat16* __restrict__ Blo,
              const float* __restrict__ bias,
              int K, int Npitch, int mode,
              float* __restrict__ outF,
              __nv_bfloat16* __restrict__ outHi,
              __nv_bfloat16* __restrict__ outLo)
{
    extern __shared__ char smem[];
    const uint32_t sb = smem_u32(smem);

    const int tid   = threadIdx.x;
    const int lane  = tid & 31;
    const int w     = tid >> 5;
    const int warpM = w >> 2;          // 0..1
    const int warpN = w & 3;           // 0..3
    const int g     = lane >> 2;       // 0..7
    const int tig   = lane & 3;        // 0..3

    const int rowA0 = blockIdx.y * BM;
    const int colB0 = blockIdx.x * BN;
    const int nch   = K / KC;

    float acc[4][4][4];
    #pragma unroll
    for (int mf = 0; mf < 4; mf++)
        #pragma unroll
        for (int nf = 0; nf < 4; nf++)
            #pragma unroll
            for (int e = 0; e < 4; e++)
                acc[mf][nf][e] = 0.0f;

    // ---- chunk loader: 4 tiles (Ahi/Alo/Bhi/Blo), 16B cp.async, SW128 ----
    auto load_chunk = [&](int j, int p) {
        const uint32_t stage = sb + p * STAGE_BYTES;
        const size_t cOff = (size_t)j * KC;   // element offset in K
        #pragma unroll
        for (int u = 0; u < 8; u++) {         // 1024 segs / 128 threads... 8 per
            const int seg = u * 256 + tid;    // 0..2047 over two tiles
            const int r = seg >> 4;           // 0..127
            const int halfsel = (seg >> 3) & 1; // 0: hi, 1: lo
            const int s = (seg & 7) << 4;     // 0..112
            const uint32_t sw = SW128(r * 128 + s);
            {   // A tiles
                const __nv_bfloat16* base = halfsel ? Alo : Ahi;
                const char* gp = (const char*)(base + (size_t)(rowA0 + r) * K + cOff) + s;
                CPA16(stage + (halfsel ? S_A_LO : S_A_HI) + sw, gp);
            }
            {   // B tiles
                const __nv_bfloat16* base = halfsel ? Blo : Bhi;
                const char* gp = (const char*)(base + (size_t)(colB0 + r) * K + cOff) + s;
                CPA16(stage + (halfsel ? S_B_LO : S_B_HI) + sw, gp);
            }
        }
        asm volatile("cp.async.commit_group;");
    };

    // ---- pipelined main loop ----
    load_chunk(0, 0);
    for (int j = 0; j < nch; j++) {
        const int p = j & 1;
        if (j + 1 < nch) {
            load_chunk(j + 1, (j + 1) & 1);
            asm volatile("cp.async.wait_group 1;" ::: "memory");
        } else {
            asm volatile("cp.async.wait_group 0;" ::: "memory");
        }
        __syncthreads();

        const uint32_t stage = sb + p * STAGE_BYTES;

        // ldmatrix lane addressing (constant per thread, varies by ks)
        const int aRow = warpM * 64 + (lane & 7) + ((lane >> 3) & 1) * 8;
        const int aKb  = ((lane >> 4) & 1) * 16;
        const int bRowBase = warpN * 32 + ((lane >> 4) & 1) * 8 + (lane & 7);
        const int bKb  = ((lane >> 3) & 1) * 16;

        #pragma unroll
        for (int ks = 0; ks < 4; ks++) {
            const int kbyte = ks * 32;
            uint32_t ah[4][4], al[4][4];
            #pragma unroll
            for (int mf = 0; mf < 4; mf++) {
                const uint32_t off = SW128((aRow + mf * 16) * 128 + kbyte + aKb);
                LDMX4(ah[mf][0], ah[mf][1], ah[mf][2], ah[mf][3],
                      stage + S_A_HI + off);
                LDMX4(al[mf][0], al[mf][1], al[mf][2], al[mf][3],
                      stage + S_A_LO + off);
            }
            uint32_t bh[4][2], bl[4][2];
            #pragma unroll
            for (int np = 0; np < 2; np++) {
                const uint32_t off = SW128((bRowBase + np * 16) * 128 + kbyte + bKb);
                uint32_t r0, r1, r2, r3;
                LDMX4(r0, r1, r2, r3, stage + S_B_HI + off);
                bh[2 * np][0] = r0; bh[2 * np][1] = r1;
                bh[2 * np + 1][0] = r2; bh[2 * np + 1][1] = r3;
                LDMX4(r0, r1, r2, r3, stage + S_B_LO + off);
                bl[2 * np][0] = r0; bl[2 * np][1] = r1;
                bl[2 * np + 1][0] = r2; bl[2 * np + 1][1] = r3;
            }
            #pragma unroll
            for (int mf = 0; mf < 4; mf++)
                #pragma unroll
                for (int nf = 0; nf < 4; nf++) {
                    MMA16816(acc[mf][nf], ah[mf], bh[nf]);   // hi*hi
                    MMA16816(acc[mf][nf], ah[mf], bl[nf]);   // hi*lo
                    MMA16816(acc[mf][nf], al[mf], bh[nf]);   // lo*hi
                }
        }
        __syncthreads();
    }

    // ---- epilogue: bias + relu straight from registers ----
    #pragma unroll
    for (int mf = 0; mf < 4; mf++) {
        const int r0 = rowA0 + warpM * 64 + mf * 16 + g;
        const int r1 = r0 + 8;
        #pragma unroll
        for (int nf = 0; nf < 4; nf++) {
            const int col = colB0 + warpN * 32 + nf * 8 + tig * 2;
            const float bx = __ldg(bias + col);
            const float by = __ldg(bias + col + 1);
            float v0x = fmaxf(acc[mf][nf][0] + bx, 0.0f);
            float v0y = fmaxf(acc[mf][nf][1] + by, 0.0f);
            float v1x = fmaxf(acc[mf][nf][2] + bx, 0.0f);
            float v1y = fmaxf(acc[mf][nf][3] + by, 0.0f);
            if (mode) {
                __nv_bfloat162 h0, l0, h1, l1;
                h0.x = __float2bfloat16(v0x);
                h0.y = __float2bfloat16(v0y);
                l0.x = __float2bfloat16(v0x - __bfloat162float(h0.x));
                l0.y = __float2bfloat16(v0y - __bfloat162float(h0.y));
                h1.x = __float2bfloat16(v1x);
                h1.y = __float2bfloat16(v1y);
                l1.x = __float2bfloat16(v1x - __bfloat162float(h1.x));
                l1.y = __float2bfloat16(v1y - __bfloat162float(h1.y));
                *(__nv_bfloat162*)(outHi + (size_t)r0 * Npitch + col) = h0;
                *(__nv_bfloat162*)(outLo + (size_t)r0 * Npitch + col) = l0;
                *(__nv_bfloat162*)(outHi + (size_t)r1 * Npitch + col) = h1;
                *(__nv_bfloat162*)(outLo + (size_t)r1 * Npitch + col) = l1;
            } else {
                *(float2*)(outF + (size_t)r0 * Npitch + col) = make_float2(v0x, v0y);
                *(float2*)(outF + (size_t)r1 * Npitch + col) = make_float2(v1x, v1y);
            }
        }
    }
}

// ---------------------------------------------------------------------------
// GEMV: scores[r] = dot(H[r,:], w) + b
// ---------------------------------------------------------------------------
__global__ __launch_bounds__(256)
void gemv_scores(const float* __restrict__ H,
                 const float* __restrict__ w,
                 const float* __restrict__ b3,
                 float* __restrict__ scores,
                 int rows, int K)
{
    const int gwarp = (blockIdx.x * blockDim.x + threadIdx.x) >> 5;
    const int lane  = threadIdx.x & 31;
    if (gwarp >= rows) return;

    const float4* r4 = (const float4*)(H + (size_t)gwarp * K);
    const float4* w4 = (const float4*)w;
    const int K4 = K >> 2;

    float acc = 0.0f;
    for (int t = lane; t < K4; t += 32) {
        float4 a = r4[t];
        float4 b = w4[t];
        acc += a.x * b.x + a.y * b.y + a.z * b.z + a.w * b.w;
    }
    #pragma unroll
    for (int o = 16; o > 0; o >>= 1)
        acc += __shfl_down_sync(0xffffffffu, acc, o);
    if (lane == 0) scores[gwarp] = acc + b3[0];
}

// ---------------------------------------------------------------------------
// soft_rank (measured 1.3us)
// ---------------------------------------------------------------------------
__global__ void softrank_kernel(const float* __restrict__ scores,
                                float* __restrict__ out,
                                int n)
{
    extern __shared__ double dyn[];
    double* bsum  = dyn;
    float*  s     = (float*)(bsum + n);
    float*  dual  = s + n;
    int*    idx   = (int*)(dual + n);
    int*    bst   = idx + n;
    int*    bcn   = bst + n;

    const int tid = threadIdx.x;
    const int nt  = blockDim.x;

    for (int i = tid; i < n; i += nt) { s[i] = scores[i]; idx[i] = i; }
    __syncthreads();

    for (int k = 2; k <= n; k <<= 1) {
        for (int j = k >> 1; j > 0; j >>= 1) {
            for (int i = tid; i < n; i += nt) {
                int ixj = i ^ j;
                if (ixj > i) {
                    bool up = ((i & k) == 0);
                    float a = s[i], b = s[ixj];
                    bool sw = up ? (a < b) : (a > b);
                    if (sw) {
                        s[i] = b; s[ixj] = a;
                        int t = idx[i]; idx[i] = idx[ixj]; idx[ixj] = t;
                    }
                }
            }
            __syncthreads();
        }
    }

    if (tid == 0) {
        int top = -1;
        double cur_sum = (double)s[0] - (double)n;
        int cur_cnt = 1, cur_start = 0;

        for (int i = 1; i < n; i++) {
            double nsum = (double)s[i] - (double)(n - i);
            int ncnt = 1, nstart = i;
            while (cur_cnt > 0 &&
                   cur_sum * (double)ncnt < nsum * (double)cur_cnt) {
                nsum += cur_sum; ncnt += cur_cnt; nstart = cur_start;
                if (top >= 0) {
                    cur_sum = bsum[top]; cur_cnt = bcn[top]; cur_start = bst[top];
                    top--;
                } else {
                    cur_cnt = 0;
                }
            }
            if (cur_cnt > 0) {
                top++;
                bsum[top] = cur_sum; bcn[top] = cur_cnt; bst[top] = cur_start;
            }
            cur_sum = nsum; cur_cnt = ncnt; cur_start = nstart;
        }
        top++;
        bsum[top] = cur_sum; bcn[top] = cur_cnt; bst[top] = cur_start;

        for (int b = 0; b <= top; b++) {
            float mean = (float)(bsum[b] / (double)bcn[b]);
            int st = bst[b], en = st + bcn[b];
            for (int t = st; t < en; t++) dual[t] = mean;
        }
    }
    __syncthreads();

    for (int i = tid; i < n; i += nt) {
        out[idx[i]] = s[i] - dual[i];
        out[n + i]  = scores[i];
    }
}

// ---------------------------------------------------------------------------
// Launch
// ---------------------------------------------------------------------------
extern "C" void kernel_launch(void* const* d_in, const int* in_sizes, int n_in,
                              void* d_out, int out_size)
{
    const float* x  = (const float*)d_in[0];
    const float* W1 = (const float*)d_in[1];
    const float* b1 = (const float*)d_in[2];
    const float* W2 = (const float*)d_in[3];
    const float* b2 = (const float*)d_in[4];
    const float* W3 = (const float*)d_in[5];
    const float* b3 = (const float*)d_in[6];
    float* out = (float*)d_out;

    __nv_bfloat16 *xhi, *xlo, *w1hi, *w1lo, *w2hi, *w2lo, *h1hi, *h1lo;
    float *h2, *sc;
    cudaGetSymbolAddress((void**)&xhi,  g_xhi);
    cudaGetSymbolAddress((void**)&xlo,  g_xlo);
    cudaGetSymbolAddress((void**)&w1hi, g_w1hi);
    cudaGetSymbolAddress((void**)&w1lo, g_w1lo);
    cudaGetSymbolAddress((void**)&w2hi, g_w2hi);
    cudaGetSymbolAddress((void**)&w2lo, g_w2lo);
    cudaGetSymbolAddress((void**)&h1hi, g_h1hi);
    cudaGetSymbolAddress((void**)&h1lo, g_h1lo);
    cudaGetSymbolAddress((void**)&h2,   g_h2);
    cudaGetSymbolAddress((void**)&sc,   g_scores);

    // conversions
    {
        int n = MB * DIN;
        split_rows<<<(n / 4 + 255) / 256, 256>>>(x, xhi, xlo, n);
        transpose_split<<<dim3(HID / 32, DIN / 32), dim3(32, 8)>>>(W1, w1hi, w1lo, DIN, HID);
        transpose_split<<<dim3(HID / 32, HID / 32), dim3(32, 8)>>>(W2, w2hi, w2lo, HID, HID);
    }

    cudaFuncSetAttribute(gemm_mma,
                         cudaFuncAttributeMaxDynamicSharedMemorySize, GEMM_SMEM);

    // layer 1: relu(x @ W1 + b1) -> h1 (split bf16)
    {
        dim3 grid(HID / BN, MB / BM);
        gemm_mma<<<grid, 256, GEMM_SMEM>>>(xhi, xlo, w1hi, w1lo, b1,
                                           DIN, HID, 1,
                                           nullptr, h1hi, h1lo);
    }
    // layer 2: relu(h1 @ W2 + b2) -> h2 (fp32)
    {
        dim3 grid(HID / BN, MB / BM);
        gemm_mma<<<grid, 256, GEMM_SMEM>>>(h1hi, h1lo, w2hi, w2lo, b2,
                                           HID, HID, 0,
                                           h2, nullptr, nullptr);
    }
    // layer 3: GEMV
    {
        int blocks = (MB + 7) / 8;
        gemv_scores<<<blocks, 256>>>(h2, W3, b3, sc, MB, HID);
    }
    // soft_rank
    {
        size_t smem = (size_t)MB * sizeof(double)
                    + (size_t)MB * sizeof(float) * 2
                    + (size_t)MB * sizeof(int) * 3;
        cudaFuncSetAttribute(softrank_kernel,
                             cudaFuncAttributeMaxDynamicSharedMemorySize,
                             (int)smem);
        softrank_kernel<<<1, 1024, smem>>>(sc, out, MB);
    }
}

// round 4
// speedup vs baseline: 5.4016x; 3.8588x over previous
#include <cuda_runtime.h>
#include <cuda_bf16.h>
#include <cstdint>

// ---------------------------------------------------------------------------
// Shapes (fixed by the dataset)
// ---------------------------------------------------------------------------
#define MB   4096
#define DIN  512
#define HID  2048

// ---------------------------------------------------------------------------
// Device scratch
// ---------------------------------------------------------------------------
__device__ __nv_bfloat16 g_xhi[(size_t)MB * DIN],  g_xlo[(size_t)MB * DIN];
__device__ __nv_bfloat16 g_w1hi[(size_t)HID * DIN], g_w1lo[(size_t)HID * DIN];
__device__ __nv_bfloat16 g_w2hi[(size_t)HID * HID], g_w2lo[(size_t)HID * HID];
__device__ __nv_bfloat16 g_h1hi[(size_t)MB * HID],  g_h1lo[(size_t)MB * HID];
__device__ float g_h2[(size_t)MB * HID];
__device__ float g_scores[MB];

// ---------------------------------------------------------------------------
// Helpers
// ---------------------------------------------------------------------------
__device__ __forceinline__ uint32_t smem_u32(const void* p) {
    uint32_t a;
    asm("{ .reg .u64 t; cvta.to.shared.u64 t, %1; cvt.u32.u64 %0, t; }"
        : "=r"(a) : "l"(p));
    return a;
}

#define SW128(o) ((o) ^ (((o) >> 3) & 0x70))

#define CPA16(smem, gptr) \
    asm volatile("cp.async.cg.shared.global [%0], [%1], 16;" \
                 :: "r"(smem), "l"(gptr))

#define LDMX4(r0, r1, r2, r3, addr) \
    asm volatile("ldmatrix.sync.aligned.m8n8.x4.shared.b16 {%0,%1,%2,%3}, [%4];" \
                 : "=r"(r0), "=r"(r1), "=r"(r2), "=r"(r3) : "r"(addr))

#define MMA16816(c, a, b) \
    asm volatile("mma.sync.aligned.m16n8k16.row.col.f32.bf16.bf16.f32 " \
                 "{%0,%1,%2,%3}, {%4,%5,%6,%7}, {%8,%9}, {%0,%1,%2,%3};" \
                 : "+f"((c)[0]), "+f"((c)[1]), "+f"((c)[2]), "+f"((c)[3]) \
                 : "r"((a)[0]), "r"((a)[1]), "r"((a)[2]), "r"((a)[3]), \
                   "r"((b)[0]), "r"((b)[1]))

// ---------------------------------------------------------------------------
// Conversion kernels: fp32 -> (bf16 hi, bf16 lo)
// ---------------------------------------------------------------------------
__global__ void split_rows(const float* __restrict__ in,
                           __nv_bfloat16* __restrict__ hi,
                           __nv_bfloat16* __restrict__ lo, int n)
{
    int i = (blockIdx.x * blockDim.x + threadIdx.x) * 4;
    if (i >= n) return;
    float4 v = *(const float4*)(in + i);
    float vv[4] = {v.x, v.y, v.z, v.w};
    #pragma unroll
    for (int k = 0; k < 4; k++) {
        __nv_bfloat16 h = __float2bfloat16(vv[k]);
        hi[i + k] = h;
        lo[i + k] = __float2bfloat16(vv[k] - __bfloat162float(h));
    }
}

// W [K,N] row-major -> T hi/lo [N,K]
__global__ void transpose_split(const float* __restrict__ W,
                                __nv_bfloat16* __restrict__ Thi,
                                __nv_bfloat16* __restrict__ Tlo,
                                int K, int N)
{
    __shared__ float t[32][33];
    int n0 = blockIdx.x * 32, k0 = blockIdx.y * 32;
    int tx = threadIdx.x, ty = threadIdx.y;
    #pragma unroll
    for (int r = ty; r < 32; r += 8)
        t[r][tx] = W[(size_t)(k0 + r) * N + n0 + tx];
    __syncthreads();
    #pragma unroll
    for (int r = ty; r < 32; r += 8) {
        float v = t[tx][r];
        __nv_bfloat16 h = __float2bfloat16(v);
        __nv_bfloat16 l = __float2bfloat16(v - __bfloat162float(h));
        size_t o = (size_t)(n0 + r) * K + k0 + tx;
        Thi[o] = h;
        Tlo[o] = l;
    }
}

// ---------------------------------------------------------------------------
// mma.sync GEMM (identical to R3): D = relu(A @ B^T + bias), split-bf16.
// ---------------------------------------------------------------------------
#define BM 128
#define BN 128
#define KC 64
#define S_A_HI 0
#define S_A_LO 16384
#define S_B_HI 32768
#define S_B_LO 49152
#define STAGE_BYTES 65536
#define GEMM_SMEM (2 * STAGE_BYTES)

__global__ __launch_bounds__(256, 1)
void gemm_mma(const __nv_bfloat16* __restrict__ Ahi,
              const __nv_bfloat16* __restrict__ Alo,
              const __nv_bfloat16* __restrict__ Bhi,
              const __nv_bfloat16* __restrict__ Blo,
              const float* __restrict__ bias,
              int K, int Npitch, int mode,
              float* __restrict__ outF,
              __nv_bfloat16* __restrict__ outHi,
              __nv_bfloat16* __restrict__ outLo)
{
    extern __shared__ char smem[];
    const uint32_t sb = smem_u32(smem);

    const int tid   = threadIdx.x;
    const int lane  = tid & 31;
    const int w     = tid >> 5;
    const int warpM = w >> 2;
    const int warpN = w & 3;
    const int g     = lane >> 2;
    const int tig   = lane & 3;

    const int rowA0 = blockIdx.y * BM;
    const int colB0 = blockIdx.x * BN;
    const int nch   = K / KC;

    float acc[4][4][4];
    #pragma unroll
    for (int mf = 0; mf < 4; mf++)
        #pragma unroll
        for (int nf = 0; nf < 4; nf++)
            #pragma unroll
            for (int e = 0; e < 4; e++)
                acc[mf][nf][e] = 0.0f;

    auto load_chunk = [&](int j, int p) {
        const uint32_t stage = sb + p * STAGE_BYTES;
        const size_t cOff = (size_t)j * KC;
        #pragma unroll
        for (int u = 0; u < 8; u++) {
            const int seg = u * 256 + tid;
            const int r = seg >> 4;
            const int halfsel = (seg >> 3) & 1;
            const int s = (seg & 7) << 4;
            const uint32_t sw = SW128(r * 128 + s);
            {
                const __nv_bfloat16* base = halfsel ? Alo : Ahi;
                const char* gp = (const char*)(base + (size_t)(rowA0 + r) * K + cOff) + s;
                CPA16(stage + (halfsel ? S_A_LO : S_A_HI) + sw, gp);
            }
            {
                const __nv_bfloat16* base = halfsel ? Blo : Bhi;
                const char* gp = (const char*)(base + (size_t)(colB0 + r) * K + cOff) + s;
                CPA16(stage + (halfsel ? S_B_LO : S_B_HI) + sw, gp);
            }
        }
        asm volatile("cp.async.commit_group;");
    };

    load_chunk(0, 0);
    for (int j = 0; j < nch; j++) {
        const int p = j & 1;
        if (j + 1 < nch) {
            load_chunk(j + 1, (j + 1) & 1);
            asm volatile("cp.async.wait_group 1;" ::: "memory");
        } else {
            asm volatile("cp.async.wait_group 0;" ::: "memory");
        }
        __syncthreads();

        const uint32_t stage = sb + p * STAGE_BYTES;

        const int aRow = warpM * 64 + (lane & 7) + ((lane >> 3) & 1) * 8;
        const int aKb  = ((lane >> 4) & 1) * 16;
        const int bRowBase = warpN * 32 + ((lane >> 4) & 1) * 8 + (lane & 7);
        const int bKb  = ((lane >> 3) & 1) * 16;

        #pragma unroll
        for (int ks = 0; ks < 4; ks++) {
            const int kbyte = ks * 32;
            uint32_t ah[4][4], al[4][4];
            #pragma unroll
            for (int mf = 0; mf < 4; mf++) {
                const uint32_t off = SW128((aRow + mf * 16) * 128 + kbyte + aKb);
                LDMX4(ah[mf][0], ah[mf][1], ah[mf][2], ah[mf][3],
                      stage + S_A_HI + off);
                LDMX4(al[mf][0], al[mf][1], al[mf][2], al[mf][3],
                      stage + S_A_LO + off);
            }
            uint32_t bh[4][2], bl[4][2];
            #pragma unroll
            for (int np = 0; np < 2; np++) {
                const uint32_t off = SW128((bRowBase + np * 16) * 128 + kbyte + bKb);
                uint32_t r0, r1, r2, r3;
                LDMX4(r0, r1, r2, r3, stage + S_B_HI + off);
                bh[2 * np][0] = r0; bh[2 * np][1] = r1;
                bh[2 * np + 1][0] = r2; bh[2 * np + 1][1] = r3;
                LDMX4(r0, r1, r2, r3, stage + S_B_LO + off);
                bl[2 * np][0] = r0; bl[2 * np][1] = r1;
                bl[2 * np + 1][0] = r2; bl[2 * np + 1][1] = r3;
            }
            #pragma unroll
            for (int mf = 0; mf < 4; mf++)
                #pragma unroll
                for (int nf = 0; nf < 4; nf++) {
                    MMA16816(acc[mf][nf], ah[mf], bh[nf]);
                    MMA16816(acc[mf][nf], ah[mf], bl[nf]);
                    MMA16816(acc[mf][nf], al[mf], bh[nf]);
                }
        }
        __syncthreads();
    }

    #pragma unroll
    for (int mf = 0; mf < 4; mf++) {
        const int r0 = rowA0 + warpM * 64 + mf * 16 + g;
        const int r1 = r0 + 8;
        #pragma unroll
        for (int nf = 0; nf < 4; nf++) {
            const int col = colB0 + warpN * 32 + nf * 8 + tig * 2;
            const float bx = __ldg(bias + col);
            const float by = __ldg(bias + col + 1);
            float v0x = fmaxf(acc[mf][nf][0] + bx, 0.0f);
            float v0y = fmaxf(acc[mf][nf][1] + by, 0.0f);
            float v1x = fmaxf(acc[mf][nf][2] + bx, 0.0f);
            float v1y = fmaxf(acc[mf][nf][3] + by, 0.0f);
            if (mode) {
                __nv_bfloat162 h0, l0, h1, l1;
                h0.x = __float2bfloat16(v0x);
                h0.y = __float2bfloat16(v0y);
                l0.x = __float2bfloat16(v0x - __bfloat162float(h0.x));
                l0.y = __float2bfloat16(v0y - __bfloat162float(h0.y));
                h1.x = __float2bfloat16(v1x);
                h1.y = __float2bfloat16(v1y);
                l1.x = __float2bfloat16(v1x - __bfloat162float(h1.x));
                l1.y = __float2bfloat16(v1y - __bfloat162float(h1.y));
                *(__nv_bfloat162*)(outHi + (size_t)r0 * Npitch + col) = h0;
                *(__nv_bfloat162*)(outLo + (size_t)r0 * Npitch + col) = l0;
                *(__nv_bfloat162*)(outHi + (size_t)r1 * Npitch + col) = h1;
                *(__nv_bfloat162*)(outLo + (size_t)r1 * Npitch + col) = l1;
            } else {
                *(float2*)(outF + (size_t)r0 * Npitch + col) = make_float2(v0x, v0y);
                *(float2*)(outF + (size_t)r1 * Npitch + col) = make_float2(v1x, v1y);
            }
        }
    }
}

// ---------------------------------------------------------------------------
// GEMV: scores[r] = dot(H[r,:], w) + b
// ---------------------------------------------------------------------------
__global__ __launch_bounds__(256)
void gemv_scores(const float* __restrict__ H,
                 const float* __restrict__ w,
                 const float* __restrict__ b3,
                 float* __restrict__ scores,
                 int rows, int K)
{
    const int gwarp = (blockIdx.x * blockDim.x + threadIdx.x) >> 5;
    const int lane  = threadIdx.x & 31;
    if (gwarp >= rows) return;

    const float4* r4 = (const float4*)(H + (size_t)gwarp * K);
    const float4* w4 = (const float4*)w;
    const int K4 = K >> 2;

    float acc = 0.0f;
    for (int t = lane; t < K4; t += 32) {
        float4 a = r4[t];
        float4 b = w4[t];
        acc += a.x * b.x + a.y * b.y + a.z * b.z + a.w * b.w;
    }
    #pragma unroll
    for (int o = 16; o > 0; o >>= 1)
        acc += __shfl_down_sync(0xffffffffu, acc, o);
    if (lane == 0) scores[gwarp] = acc + b3[0];
}

// ---------------------------------------------------------------------------
// soft_rank, fully parallel (no FP64, no serial O(n) loops):
//   1. bitonic sort (desc) of (s, idx) in shared
//   2. PAV via parallel merge tree: 12 levels of segment-doubling; each merge
//      resolves boundary pooling in-place on a compact pool stack.
//      In-place safety: pushing the t-th right record writes index
//      <= Lbase + nl + t while record t is read from Lbase + s + t (nl <= s,
//      read-before-write per record).
//   3. dual expansion by parallel binary search over pool starts
// ---------------------------------------------------------------------------
__device__ __forceinline__ int pav_merge(int Lbase, int nl, int Rbase, int nr,
                                         int* __restrict__ pst,
                                         int* __restrict__ pcn,
                                         float* __restrict__ psm)
{
    int len = nl;
    for (int t = 0; t < nr; t++) {
        int   cs = pst[Rbase + t];
        int   cc = pcn[Rbase + t];
        float cm = psm[Rbase + t];
        while (len > 0) {
            float ts = psm[Lbase + len - 1];
            int   tc = pcn[Lbase + len - 1];
            // violation (nonincreasing needed): mean(top) < mean(cur)
            if (ts * (float)cc < cm * (float)tc) {
                cm += ts; cc += tc; cs = pst[Lbase + len - 1];
                len--;
            } else break;
        }
        pst[Lbase + len] = cs;
        pcn[Lbase + len] = cc;
        psm[Lbase + len] = cm;
        len++;
    }
    return len;
}

__global__ void softrank_kernel(const float* __restrict__ scores,
                                float* __restrict__ out,
                                int n)
{
    extern __shared__ float smf[];
    float* s   = smf;                 // n
    float* psm = s + n;               // n : pool sums
    int*   idx = (int*)(psm + n);     // n
    int*   pst = idx + n;             // n : pool start
    int*   pcn = pst + n;             // n : pool count
    int*   cA  = pcn + n;             // n/2 : per-segment pool counts
    int*   cB  = cA + n / 2;          // n/2

    const int tid = threadIdx.x;
    const int nt  = blockDim.x;

    for (int i = tid; i < n; i += nt) { s[i] = scores[i]; idx[i] = i; }
    __syncthreads();

    // ---- bitonic sort, descending ----
    for (int k = 2; k <= n; k <<= 1) {
        for (int j = k >> 1; j > 0; j >>= 1) {
            for (int i = tid; i < n; i += nt) {
                int ixj = i ^ j;
                if (ixj > i) {
                    bool up = ((i & k) == 0);
                    float a = s[i], b = s[ixj];
                    bool sw = up ? (a < b) : (a > b);
                    if (sw) {
                        s[i] = b; s[ixj] = a;
                        int t = idx[i]; idx[i] = idx[ixj]; idx[ixj] = t;
                    }
                }
            }
            __syncthreads();
        }
    }

    // ---- level-0 pools: y[i] = s[i] - (n - i) ----
    for (int i = tid; i < n; i += nt) {
        pst[i] = i;
        pcn[i] = 1;
        psm[i] = s[i] - (float)(n - i);
    }
    __syncthreads();

    // ---- level 1: merge singleton pairs ----
    for (int g2 = tid; g2 < n / 2; g2 += nt)
        cA[g2] = pav_merge(2 * g2, 1, 2 * g2 + 1, 1, pst, pcn, psm);
    __syncthreads();

    // ---- levels 2..log2(n) ----
    int* cCur = cA;
    int* cNxt = cB;
    for (int L = 2; (1 << L) <= n; L++) {
        const int half = 1 << (L - 1);
        const int nm = n >> L;
        for (int g2 = tid; g2 < nm; g2 += nt)
            cNxt[g2] = pav_merge((g2 << L), cCur[2 * g2],
                                 (g2 << L) + half, cCur[2 * g2 + 1],
                                 pst, pcn, psm);
        __syncthreads();
        int* t = cCur; cCur = cNxt; cNxt = t;
    }
    const int P = cCur[0];

    // ---- expansion + scatter ----
    for (int i = tid; i < n; i += nt) {
        int lo = 0, hi = P - 1;
        while (lo < hi) {
            int mid = (lo + hi + 1) >> 1;
            if (pst[mid] <= i) lo = mid; else hi = mid - 1;
        }
        float dual = psm[lo] / (float)pcn[lo];
        out[idx[i]] = s[i] - dual;      // rank, original order
        out[n + i]  = scores[i];        // scores passthrough
    }
}

// ---------------------------------------------------------------------------
// Launch
// ---------------------------------------------------------------------------
extern "C" void kernel_launch(void* const* d_in, const int* in_sizes, int n_in,
                              void* d_out, int out_size)
{
    const float* x  = (const float*)d_in[0];
    const float* W1 = (const float*)d_in[1];
    const float* b1 = (const float*)d_in[2];
    const float* W2 = (const float*)d_in[3];
    const float* b2 = (const float*)d_in[4];
    const float* W3 = (const float*)d_in[5];
    const float* b3 = (const float*)d_in[6];
    float* out = (float*)d_out;

    __nv_bfloat16 *xhi, *xlo, *w1hi, *w1lo, *w2hi, *w2lo, *h1hi, *h1lo;
    float *h2, *sc;
    cudaGetSymbolAddress((void**)&xhi,  g_xhi);
    cudaGetSymbolAddress((void**)&xlo,  g_xlo);
    cudaGetSymbolAddress((void**)&w1hi, g_w1hi);
    cudaGetSymbolAddress((void**)&w1lo, g_w1lo);
    cudaGetSymbolAddress((void**)&w2hi, g_w2hi);
    cudaGetSymbolAddress((void**)&w2lo, g_w2lo);
    cudaGetSymbolAddress((void**)&h1hi, g_h1hi);
    cudaGetSymbolAddress((void**)&h1lo, g_h1lo);
    cudaGetSymbolAddress((void**)&h2,   g_h2);
    cudaGetSymbolAddress((void**)&sc,   g_scores);

    // conversions
    {
        int n = MB * DIN;
        split_rows<<<(n / 4 + 255) / 256, 256>>>(x, xhi, xlo, n);
        transpose_split<<<dim3(HID / 32, DIN / 32), dim3(32, 8)>>>(W1, w1hi, w1lo, DIN, HID);
        transpose_split<<<dim3(HID / 32, HID / 32), dim3(32, 8)>>>(W2, w2hi, w2lo, HID, HID);
    }

    cudaFuncSetAttribute(gemm_mma,
                         cudaFuncAttributeMaxDynamicSharedMemorySize, GEMM_SMEM);

    // layer 1: relu(x @ W1 + b1) -> h1 (split bf16)
    {
        dim3 grid(HID / BN, MB / BM);
        gemm_mma<<<grid, 256, GEMM_SMEM>>>(xhi, xlo, w1hi, w1lo, b1,
                                           DIN, HID, 1,
                                           nullptr, h1hi, h1lo);
    }
    // layer 2: relu(h1 @ W2 + b2) -> h2 (fp32)
    {
        dim3 grid(HID / BN, MB / BM);
        gemm_mma<<<grid, 256, GEMM_SMEM>>>(h1hi, h1lo, w2hi, w2lo, b2,
                                           HID, HID, 0,
                                           h2, nullptr, nullptr);
    }
    // layer 3: GEMV
    {
        int blocks = (MB + 7) / 8;
        gemv_scores<<<blocks, 256>>>(h2, W3, b3, sc, MB, HID);
    }
    // soft_rank (parallel PAV)
    {
        // floats/ints: 5n + n = 4096*6 words = 96 KB
        size_t smem = (size_t)MB * 6 * sizeof(float);
        cudaFuncSetAttribute(softrank_kernel,
                             cudaFuncAttributeMaxDynamicSharedMemorySize,
                             (int)smem);
        softrank_kernel<<<1, 1024, smem>>>(sc, out, MB);
    }
}

// round 5
// speedup vs baseline: 5.5357x; 1.0248x over previous
#include <cuda_runtime.h>
#include <cuda_bf16.h>
#include <cstdint>

// ---------------------------------------------------------------------------
// Shapes (fixed by the dataset)
// ---------------------------------------------------------------------------
#define MB   4096
#define DIN  512
#define HID  2048

// ---------------------------------------------------------------------------
// Device scratch
// ---------------------------------------------------------------------------
__device__ __nv_bfloat16 g_xhi[(size_t)MB * DIN],  g_xlo[(size_t)MB * DIN];
__device__ __nv_bfloat16 g_w1hi[(size_t)HID * DIN], g_w1lo[(size_t)HID * DIN];
__device__ __nv_bfloat16 g_w2hi[(size_t)HID * HID], g_w2lo[(size_t)HID * HID];
__device__ __nv_bfloat16 g_h1hi[(size_t)MB * HID],  g_h1lo[(size_t)MB * HID];
__device__ float g_h2[(size_t)MB * HID];
__device__ float g_scores[MB];

// ---------------------------------------------------------------------------
// Helpers
// ---------------------------------------------------------------------------
__device__ __forceinline__ uint32_t smem_u32(const void* p) {
    uint32_t a;
    asm("{ .reg .u64 t; cvta.to.shared.u64 t, %1; cvt.u32.u64 %0, t; }"
        : "=r"(a) : "l"(p));
    return a;
}

#define SW128(o) ((o) ^ (((o) >> 3) & 0x70))

#define CPA16(smem, gptr) \
    asm volatile("cp.async.cg.shared.global [%0], [%1], 16;" \
                 :: "r"(smem), "l"(gptr))

#define LDMX4(r0, r1, r2, r3, addr) \
    asm volatile("ldmatrix.sync.aligned.m8n8.x4.shared.b16 {%0,%1,%2,%3}, [%4];" \
                 : "=r"(r0), "=r"(r1), "=r"(r2), "=r"(r3) : "r"(addr))

#define MMA16816(c, a, b) \
    asm volatile("mma.sync.aligned.m16n8k16.row.col.f32.bf16.bf16.f32 " \
                 "{%0,%1,%2,%3}, {%4,%5,%6,%7}, {%8,%9}, {%0,%1,%2,%3};" \
                 : "+f"((c)[0]), "+f"((c)[1]), "+f"((c)[2]), "+f"((c)[3]) \
                 : "r"((a)[0]), "r"((a)[1]), "r"((a)[2]), "r"((a)[3]), \
                   "r"((b)[0]), "r"((b)[1]))

// ---------------------------------------------------------------------------
// Conversion kernels: fp32 -> (bf16 hi, bf16 lo)
// ---------------------------------------------------------------------------
__global__ void split_rows(const float* __restrict__ in,
                           __nv_bfloat16* __restrict__ hi,
                           __nv_bfloat16* __restrict__ lo, int n)
{
    int i = (blockIdx.x * blockDim.x + threadIdx.x) * 4;
    if (i >= n) return;
    float4 v = *(const float4*)(in + i);
    float vv[4] = {v.x, v.y, v.z, v.w};
    #pragma unroll
    for (int k = 0; k < 4; k++) {
        __nv_bfloat16 h = __float2bfloat16(vv[k]);
        hi[i + k] = h;
        lo[i + k] = __float2bfloat16(vv[k] - __bfloat162float(h));
    }
}

// W [K,N] row-major -> T hi/lo [N,K]
__global__ void transpose_split(const float* __restrict__ W,
                                __nv_bfloat16* __restrict__ Thi,
                                __nv_bfloat16* __restrict__ Tlo,
                                int K, int N)
{
    __shared__ float t[32][33];
    int n0 = blockIdx.x * 32, k0 = blockIdx.y * 32;
    int tx = threadIdx.x, ty = threadIdx.y;
    #pragma unroll
    for (int r = ty; r < 32; r += 8)
        t[r][tx] = W[(size_t)(k0 + r) * N + n0 + tx];
    __syncthreads();
    #pragma unroll
    for (int r = ty; r < 32; r += 8) {
        float v = t[tx][r];
        __nv_bfloat16 h = __float2bfloat16(v);
        __nv_bfloat16 l = __float2bfloat16(v - __bfloat162float(h));
        size_t o = (size_t)(n0 + r) * K + k0 + tx;
        Thi[o] = h;
        Tlo[o] = l;
    }
}

// ---------------------------------------------------------------------------
// mma.sync GEMM: D = relu(A @ B^T + bias), split-bf16, 3-stage cp.async
// pipeline (one __syncthreads per chunk, 2-chunk prefetch depth).
// ---------------------------------------------------------------------------
#define BM 128
#define BN 128
#define KC 64
#define S_A_HI 0
#define S_A_LO 16384
#define S_B_HI 32768
#define S_B_LO 49152
#define STAGE_BYTES 65536
#define NSTAGE 3
#define GEMM_SMEM (NSTAGE * STAGE_BYTES)   // 196608

__global__ __launch_bounds__(256, 1)
void gemm_mma(const __nv_bfloat16* __restrict__ Ahi,
              const __nv_bfloat16* __restrict__ Alo,
              const __nv_bfloat16* __restrict__ Bhi,
              const __nv_bfloat16* __restrict__ Blo,
              const float* __restrict__ bias,
              int K, int Npitch, int mode,
              float* __restrict__ outF,
              __nv_bfloat16* __restrict__ outHi,
              __nv_bfloat16* __restrict__ outLo)
{
    extern __shared__ char smem[];
    const uint32_t sb = smem_u32(smem);

    const int tid   = threadIdx.x;
    const int lane  = tid & 31;
    const int w     = tid >> 5;
    const int warpM = w >> 2;
    const int warpN = w & 3;
    const int g     = lane >> 2;
    const int tig   = lane & 3;

    const int rowA0 = blockIdx.y * BM;
    const int colB0 = blockIdx.x * BN;
    const int nch   = K / KC;

    float acc[4][4][4];
    #pragma unroll
    for (int mf = 0; mf < 4; mf++)
        #pragma unroll
        for (int nf = 0; nf < 4; nf++)
            #pragma unroll
            for (int e = 0; e < 4; e++)
                acc[mf][nf][e] = 0.0f;

    auto load_chunk = [&](int j, int st) {
        const uint32_t stage = sb + st * STAGE_BYTES;
        const size_t cOff = (size_t)j * KC;
        #pragma unroll
        for (int u = 0; u < 8; u++) {
            const int seg = u * 256 + tid;
            const int r = seg >> 4;
            const int halfsel = (seg >> 3) & 1;
            const int s = (seg & 7) << 4;
            const uint32_t sw = SW128(r * 128 + s);
            {
                const __nv_bfloat16* base = halfsel ? Alo : Ahi;
                const char* gp = (const char*)(base + (size_t)(rowA0 + r) * K + cOff) + s;
                CPA16(stage + (halfsel ? S_A_LO : S_A_HI) + sw, gp);
            }
            {
                const __nv_bfloat16* base = halfsel ? Blo : Bhi;
                const char* gp = (const char*)(base + (size_t)(colB0 + r) * K + cOff) + s;
                CPA16(stage + (halfsel ? S_B_LO : S_B_HI) + sw, gp);
            }
        }
        asm volatile("cp.async.commit_group;");
    };

    // ldmatrix lane addressing (constant per thread)
    const int aRow = warpM * 64 + (lane & 7) + ((lane >> 3) & 1) * 8;
    const int aKb  = ((lane >> 4) & 1) * 16;
    const int bRowBase = warpN * 32 + ((lane >> 4) & 1) * 8 + (lane & 7);
    const int bKb  = ((lane >> 3) & 1) * 16;

    // prologue: 2 chunks in flight
    load_chunk(0, 0);
    if (nch > 1) load_chunk(1, 1);

    int st = 0;
    for (int j = 0; j < nch; j++) {
        // chunk j ready (allow 1 younger group pending, except at the end)
        if (j + 1 < nch) {
            asm volatile("cp.async.wait_group 1;" ::: "memory");
        } else {
            asm volatile("cp.async.wait_group 0;" ::: "memory");
        }
        __syncthreads();   // data visible to all warps; stage st+2 free for reuse

        if (j + 2 < nch) {
            int st2 = st + 2; if (st2 >= NSTAGE) st2 -= NSTAGE;
            load_chunk(j + 2, st2);
        }

        const uint32_t stage = sb + st * STAGE_BYTES;

        #pragma unroll
        for (int ks = 0; ks < 4; ks++) {
            const int kbyte = ks * 32;
            uint32_t ah[4][4], al[4][4];
            #pragma unroll
            for (int mf = 0; mf < 4; mf++) {
                const uint32_t off = SW128((aRow + mf * 16) * 128 + kbyte + aKb);
                LDMX4(ah[mf][0], ah[mf][1], ah[mf][2], ah[mf][3],
                      stage + S_A_HI + off);
                LDMX4(al[mf][0], al[mf][1], al[mf][2], al[mf][3],
                      stage + S_A_LO + off);
            }
            uint32_t bh[4][2], bl[4][2];
            #pragma unroll
            for (int np = 0; np < 2; np++) {
                const uint32_t off = SW128((bRowBase + np * 16) * 128 + kbyte + bKb);
                uint32_t r0, r1, r2, r3;
                LDMX4(r0, r1, r2, r3, stage + S_B_HI + off);
                bh[2 * np][0] = r0; bh[2 * np][1] = r1;
                bh[2 * np + 1][0] = r2; bh[2 * np + 1][1] = r3;
                LDMX4(r0, r1, r2, r3, stage + S_B_LO + off);
                bl[2 * np][0] = r0; bl[2 * np][1] = r1;
                bl[2 * np + 1][0] = r2; bl[2 * np + 1][1] = r3;
            }
            #pragma unroll
            for (int mf = 0; mf < 4; mf++)
                #pragma unroll
                for (int nf = 0; nf < 4; nf++) {
                    MMA16816(acc[mf][nf], ah[mf], bh[nf]);
                    MMA16816(acc[mf][nf], ah[mf], bl[nf]);
                    MMA16816(acc[mf][nf], al[mf], bh[nf]);
                }
        }

        st++; if (st >= NSTAGE) st = 0;
    }

    // ---- epilogue: bias + relu straight from registers ----
    #pragma unroll
    for (int mf = 0; mf < 4; mf++) {
        const int r0 = rowA0 + warpM * 64 + mf * 16 + g;
        const int r1 = r0 + 8;
        #pragma unroll
        for (int nf = 0; nf < 4; nf++) {
            const int col = colB0 + warpN * 32 + nf * 8 + tig * 2;
            const float bx = __ldg(bias + col);
            const float by = __ldg(bias + col + 1);
            float v0x = fmaxf(acc[mf][nf][0] + bx, 0.0f);
            float v0y = fmaxf(acc[mf][nf][1] + by, 0.0f);
            float v1x = fmaxf(acc[mf][nf][2] + bx, 0.0f);
            float v1y = fmaxf(acc[mf][nf][3] + by, 0.0f);
            if (mode) {
                __nv_bfloat162 h0, l0, h1, l1;
                h0.x = __float2bfloat16(v0x);
                h0.y = __float2bfloat16(v0y);
                l0.x = __float2bfloat16(v0x - __bfloat162float(h0.x));
                l0.y = __float2bfloat16(v0y - __bfloat162float(h0.y));
                h1.x = __float2bfloat16(v1x);
                h1.y = __float2bfloat16(v1y);
                l1.x = __float2bfloat16(v1x - __bfloat162float(h1.x));
                l1.y = __float2bfloat16(v1y - __bfloat162float(h1.y));
                *(__nv_bfloat162*)(outHi + (size_t)r0 * Npitch + col) = h0;
                *(__nv_bfloat162*)(outLo + (size_t)r0 * Npitch + col) = l0;
                *(__nv_bfloat162*)(outHi + (size_t)r1 * Npitch + col) = h1;
                *(__nv_bfloat162*)(outLo + (size_t)r1 * Npitch + col) = l1;
            } else {
                *(float2*)(outF + (size_t)r0 * Npitch + col) = make_float2(v0x, v0y);
                *(float2*)(outF + (size_t)r1 * Npitch + col) = make_float2(v1x, v1y);
            }
        }
    }
}

// ---------------------------------------------------------------------------
// GEMV: scores[r] = dot(H[r,:], w) + b
// ---------------------------------------------------------------------------
__global__ __launch_bounds__(256)
void gemv_scores(const float* __restrict__ H,
                 const float* __restrict__ w,
                 const float* __restrict__ b3,
                 float* __restrict__ scores,
                 int rows, int K)
{
    const int gwarp = (blockIdx.x * blockDim.x + threadIdx.x) >> 5;
    const int lane  = threadIdx.x & 31;
    if (gwarp >= rows) return;

    const float4* r4 = (const float4*)(H + (size_t)gwarp * K);
    const float4* w4 = (const float4*)w;
    const int K4 = K >> 2;

    float acc = 0.0f;
    for (int t = lane; t < K4; t += 32) {
        float4 a = r4[t];
        float4 b = w4[t];
        acc += a.x * b.x + a.y * b.y + a.z * b.z + a.w * b.w;
    }
    #pragma unroll
    for (int o = 16; o > 0; o >>= 1)
        acc += __shfl_down_sync(0xffffffffu, acc, o);
    if (lane == 0) scores[gwarp] = acc + b3[0];
}

// ---------------------------------------------------------------------------
// soft_rank, fully parallel (bitonic sort + merge-tree PAV + binary-search
// expansion). Measured contribution small.
// ---------------------------------------------------------------------------
__device__ __forceinline__ int pav_merge(int Lbase, int nl, int Rbase, int nr,
                                         int* __restrict__ pst,
                                         int* __restrict__ pcn,
                                         float* __restrict__ psm)
{
    int len = nl;
    for (int t = 0; t < nr; t++) {
        int   cs = pst[Rbase + t];
        int   cc = pcn[Rbase + t];
        float cm = psm[Rbase + t];
        while (len > 0) {
            float ts = psm[Lbase + len - 1];
            int   tc = pcn[Lbase + len - 1];
            if (ts * (float)cc < cm * (float)tc) {
                cm += ts; cc += tc; cs = pst[Lbase + len - 1];
                len--;
            } else break;
        }
        pst[Lbase + len] = cs;
        pcn[Lbase + len] = cc;
        psm[Lbase + len] = cm;
        len++;
    }
    return len;
}

__global__ void softrank_kernel(const float* __restrict__ scores,
                                float* __restrict__ out,
                                int n)
{
    extern __shared__ float smf[];
    float* s   = smf;
    float* psm = s + n;
    int*   idx = (int*)(psm + n);
    int*   pst = idx + n;
    int*   pcn = pst + n;
    int*   cA  = pcn + n;
    int*   cB  = cA + n / 2;

    const int tid = threadIdx.x;
    const int nt  = blockDim.x;

    for (int i = tid; i < n; i += nt) { s[i] = scores[i]; idx[i] = i; }
    __syncthreads();

    for (int k = 2; k <= n; k <<= 1) {
        for (int j = k >> 1; j > 0; j >>= 1) {
            for (int i = tid; i < n; i += nt) {
                int ixj = i ^ j;
                if (ixj > i) {
                    bool up = ((i & k) == 0);
                    float a = s[i], b = s[ixj];
                    bool sw = up ? (a < b) : (a > b);
                    if (sw) {
                        s[i] = b; s[ixj] = a;
                        int t = idx[i]; idx[i] = idx[ixj]; idx[ixj] = t;
                    }
                }
            }
            __syncthreads();
        }
    }

    for (int i = tid; i < n; i += nt) {
        pst[i] = i;
        pcn[i] = 1;
        psm[i] = s[i] - (float)(n - i);
    }
    __syncthreads();

    for (int g2 = tid; g2 < n / 2; g2 += nt)
        cA[g2] = pav_merge(2 * g2, 1, 2 * g2 + 1, 1, pst, pcn, psm);
    __syncthreads();

    int* cCur = cA;
    int* cNxt = cB;
    for (int L = 2; (1 << L) <= n; L++) {
        const int half = 1 << (L - 1);
        const int nm = n >> L;
        for (int g2 = tid; g2 < nm; g2 += nt)
            cNxt[g2] = pav_merge((g2 << L), cCur[2 * g2],
                                 (g2 << L) + half, cCur[2 * g2 + 1],
                                 pst, pcn, psm);
        __syncthreads();
        int* t = cCur; cCur = cNxt; cNxt = t;
    }
    const int P = cCur[0];

    for (int i = tid; i < n; i += nt) {
        int lo = 0, hi = P - 1;
        while (lo < hi) {
            int mid = (lo + hi + 1) >> 1;
            if (pst[mid] <= i) lo = mid; else hi = mid - 1;
        }
        float dual = psm[lo] / (float)pcn[lo];
        out[idx[i]] = s[i] - dual;
        out[n + i]  = scores[i];
    }
}

// ---------------------------------------------------------------------------
// Launch
// ---------------------------------------------------------------------------
extern "C" void kernel_launch(void* const* d_in, const int* in_sizes, int n_in,
                              void* d_out, int out_size)
{
    const float* x  = (const float*)d_in[0];
    const float* W1 = (const float*)d_in[1];
    const float* b1 = (const float*)d_in[2];
    const float* W2 = (const float*)d_in[3];
    const float* b2 = (const float*)d_in[4];
    const float* W3 = (const float*)d_in[5];
    const float* b3 = (const float*)d_in[6];
    float* out = (float*)d_out;

    __nv_bfloat16 *xhi, *xlo, *w1hi, *w1lo, *w2hi, *w2lo, *h1hi, *h1lo;
    float *h2, *sc;
    cudaGetSymbolAddress((void**)&xhi,  g_xhi);
    cudaGetSymbolAddress((void**)&xlo,  g_xlo);
    cudaGetSymbolAddress((void**)&w1hi, g_w1hi);
    cudaGetSymbolAddress((void**)&w1lo, g_w1lo);
    cudaGetSymbolAddress((void**)&w2hi, g_w2hi);
    cudaGetSymbolAddress((void**)&w2lo, g_w2lo);
    cudaGetSymbolAddress((void**)&h1hi, g_h1hi);
    cudaGetSymbolAddress((void**)&h1lo, g_h1lo);
    cudaGetSymbolAddress((void**)&h2,   g_h2);
    cudaGetSymbolAddress((void**)&sc,   g_scores);

    // conversions
    {
        int n = MB * DIN;
        split_rows<<<(n / 4 + 255) / 256, 256>>>(x, xhi, xlo, n);
        transpose_split<<<dim3(HID / 32, DIN / 32), dim3(32, 8)>>>(W1, w1hi, w1lo, DIN, HID);
        transpose_split<<<dim3(HID / 32, HID / 32), dim3(32, 8)>>>(W2, w2hi, w2lo, HID, HID);
    }

    cudaFuncSetAttribute(gemm_mma,
                         cudaFuncAttributeMaxDynamicSharedMemorySize, GEMM_SMEM);

    // layer 1: relu(x @ W1 + b1) -> h1 (split bf16)
    {
        dim3 grid(HID / BN, MB / BM);
        gemm_mma<<<grid, 256, GEMM_SMEM>>>(xhi, xlo, w1hi, w1lo, b1,
                                           DIN, HID, 1,
                                           nullptr, h1hi, h1lo);
    }
    // layer 2: relu(h1 @ W2 + b2) -> h2 (fp32)
    {
        dim3 grid(HID / BN, MB / BM);
        gemm_mma<<<grid, 256, GEMM_SMEM>>>(h1hi, h1lo, w2hi, w2lo, b2,
                                           HID, HID, 0,
                                           h2, nullptr, nullptr);
    }
    // layer 3: GEMV
    {
        int blocks = (MB + 7) / 8;
        gemv_scores<<<blocks, 256>>>(h2, W3, b3, sc, MB, HID);
    }
    // soft_rank (parallel PAV)
    {
        size_t smem = (size_t)MB * 6 * sizeof(float);
        cudaFuncSetAttribute(softrank_kernel,
                             cudaFuncAttributeMaxDynamicSharedMemorySize,
                             (int)smem);
        softrank_kernel<<<1, 1024, smem>>>(sc, out, MB);
    }
}

// round 6
// speedup vs baseline: 5.8202x; 1.0514x over previous
#include <cuda_runtime.h>
#include <cuda_bf16.h>
#include <cstdint>

// ---------------------------------------------------------------------------
// Shapes (fixed by the dataset)
// ---------------------------------------------------------------------------
#define MB   4096
#define DIN  512
#define HID  2048

// ---------------------------------------------------------------------------
// Device scratch
// ---------------------------------------------------------------------------
__device__ __nv_bfloat16 g_xhi[(size_t)MB * DIN],  g_xlo[(size_t)MB * DIN];
__device__ __nv_bfloat16 g_w1hi[(size_t)HID * DIN], g_w1lo[(size_t)HID * DIN];
__device__ __nv_bfloat16 g_w2hi[(size_t)HID * HID], g_w2lo[(size_t)HID * HID];
__device__ __nv_bfloat16 g_h1hi[(size_t)MB * HID],  g_h1lo[(size_t)MB * HID];
__device__ float g_h2[(size_t)MB * HID];
__device__ float g_scores[MB];

// ---------------------------------------------------------------------------
// Helpers
// ---------------------------------------------------------------------------
__device__ __forceinline__ uint32_t smem_u32(const void* p) {
    uint32_t a;
    asm("{ .reg .u64 t; cvta.to.shared.u64 t, %1; cvt.u32.u64 %0, t; }"
        : "=r"(a) : "l"(p));
    return a;
}

#define SW128(o) ((o) ^ (((o) >> 3) & 0x70))

#define CPA16(smem, gptr) \
    asm volatile("cp.async.cg.shared.global [%0], [%1], 16;" \
                 :: "r"(smem), "l"(gptr))

#define LDMX4(r0, r1, r2, r3, addr) \
    asm volatile("ldmatrix.sync.aligned.m8n8.x4.shared.b16 {%0,%1,%2,%3}, [%4];" \
                 : "=r"(r0), "=r"(r1), "=r"(r2), "=r"(r3) : "r"(addr))

#define MMA16816(c, a0, a1, a2, a3, b0, b1) \
    asm volatile("mma.sync.aligned.m16n8k16.row.col.f32.bf16.bf16.f32 " \
                 "{%0,%1,%2,%3}, {%4,%5,%6,%7}, {%8,%9}, {%0,%1,%2,%3};" \
                 : "+f"((c)[0]), "+f"((c)[1]), "+f"((c)[2]), "+f"((c)[3]) \
                 : "r"(a0), "r"(a1), "r"(a2), "r"(a3), "r"(b0), "r"(b1))

// ---------------------------------------------------------------------------
// Conversion kernels: fp32 -> (bf16 hi, bf16 lo)
// ---------------------------------------------------------------------------
__global__ void split_rows(const float* __restrict__ in,
                           __nv_bfloat16* __restrict__ hi,
                           __nv_bfloat16* __restrict__ lo, int n)
{
    int i = (blockIdx.x * blockDim.x + threadIdx.x) * 4;
    if (i >= n) return;
    float4 v = *(const float4*)(in + i);
    float vv[4] = {v.x, v.y, v.z, v.w};
    #pragma unroll
    for (int k = 0; k < 4; k++) {
        __nv_bfloat16 h = __float2bfloat16(vv[k]);
        hi[i + k] = h;
        lo[i + k] = __float2bfloat16(vv[k] - __bfloat162float(h));
    }
}

// W [K,N] row-major -> T hi/lo [N,K]
__global__ void transpose_split(const float* __restrict__ W,
                                __nv_bfloat16* __restrict__ Thi,
                                __nv_bfloat16* __restrict__ Tlo,
                                int K, int N)
{
    __shared__ float t[32][33];
    int n0 = blockIdx.x * 32, k0 = blockIdx.y * 32;
    int tx = threadIdx.x, ty = threadIdx.y;
    #pragma unroll
    for (int r = ty; r < 32; r += 8)
        t[r][tx] = W[(size_t)(k0 + r) * N + n0 + tx];
    __syncthreads();
    #pragma unroll
    for (int r = ty; r < 32; r += 8) {
        float v = t[tx][r];
        __nv_bfloat16 h = __float2bfloat16(v);
        __nv_bfloat16 l = __float2bfloat16(v - __bfloat162float(h));
        size_t o = (size_t)(n0 + r) * K + k0 + tx;
        Thi[o] = h;
        Tlo[o] = l;
    }
}

// ---------------------------------------------------------------------------
// mma.sync GEMM: D = relu(A @ B^T + bias), split-bf16.
// CTA 128x256, warp grid 2x4, warp tile 64x64, KC=64, 2-stage cp.async.
// ---------------------------------------------------------------------------
#define BM 128
#define BN 256
#define KC 64
#define S_A_HI 0
#define S_A_LO 16384
#define S_B_HI 32768
#define S_B_LO 65536
#define STAGE_BYTES 98304
#define GEMM_SMEM (2 * STAGE_BYTES)   // 196608

__global__ __launch_bounds__(256, 1)
void gemm_mma(const __nv_bfloat16* __restrict__ Ahi,
              const __nv_bfloat16* __restrict__ Alo,
              const __nv_bfloat16* __restrict__ Bhi,
              const __nv_bfloat16* __restrict__ Blo,
              const float* __restrict__ bias,
              int K, int Npitch, int mode,
              float* __restrict__ outF,
              __nv_bfloat16* __restrict__ outHi,
              __nv_bfloat16* __restrict__ outLo)
{
    extern __shared__ char smem[];
    const uint32_t sb = smem_u32(smem);

    const int tid   = threadIdx.x;
    const int lane  = tid & 31;
    const int w     = tid >> 5;
    const int warpM = w >> 2;          // 0..1  (64 rows each)
    const int warpN = w & 3;           // 0..3  (64 cols each)
    const int g     = lane >> 2;
    const int tig   = lane & 3;

    const int rowA0 = blockIdx.y * BM;
    const int colB0 = blockIdx.x * BN;
    const int nch   = K / KC;

    float acc[4][8][4];
    #pragma unroll
    for (int mf = 0; mf < 4; mf++)
        #pragma unroll
        for (int nf = 0; nf < 8; nf++)
            #pragma unroll
            for (int e = 0; e < 4; e++)
                acc[mf][nf][e] = 0.0f;

    auto load_chunk = [&](int j, int st) {
        const uint32_t stage = sb + st * STAGE_BYTES;
        const size_t cOff = (size_t)j * KC;
        // A tiles: 128 rows x 8 segs x {hi,lo} = 2048 segs
        #pragma unroll
        for (int u = 0; u < 8; u++) {
            const int seg = u * 256 + tid;
            const int r = seg >> 4;
            const int halfsel = (seg >> 3) & 1;
            const int s = (seg & 7) << 4;
            const uint32_t sw = SW128(r * 128 + s);
            const __nv_bfloat16* base = halfsel ? Alo : Ahi;
            const char* gp = (const char*)(base + (size_t)(rowA0 + r) * K + cOff) + s;
            CPA16(stage + (halfsel ? S_A_LO : S_A_HI) + sw, gp);
        }
        // B tiles: 256 rows x 8 segs x {hi,lo} = 4096 segs
        #pragma unroll
        for (int u = 0; u < 16; u++) {
            const int seg = u * 256 + tid;
            const int r = seg >> 4;
            const int halfsel = (seg >> 3) & 1;
            const int s = (seg & 7) << 4;
            const uint32_t sw = SW128(r * 128 + s);
            const __nv_bfloat16* base = halfsel ? Blo : Bhi;
            const char* gp = (const char*)(base + (size_t)(colB0 + r) * K + cOff) + s;
            CPA16(stage + (halfsel ? S_B_LO : S_B_HI) + sw, gp);
        }
        asm volatile("cp.async.commit_group;");
    };

    // ldmatrix lane addressing
    const int aRow = warpM * 64 + (lane & 7) + ((lane >> 3) & 1) * 8;
    const int aKb  = ((lane >> 4) & 1) * 16;
    const int bRowBase = warpN * 64 + ((lane >> 4) & 1) * 8 + (lane & 7);
    const int bKb  = ((lane >> 3) & 1) * 16;

    load_chunk(0, 0);

    for (int j = 0; j < nch; j++) {
        __syncthreads();     // all warps done with stage (j+1)&1 from chunk j-1
        if (j + 1 < nch) {
            load_chunk(j + 1, (j + 1) & 1);
            asm volatile("cp.async.wait_group 1;" ::: "memory");
        } else {
            asm volatile("cp.async.wait_group 0;" ::: "memory");
        }
        __syncthreads();     // chunk j visible to all warps

        const uint32_t stage = sb + (j & 1) * STAGE_BYTES;

        #pragma unroll
        for (int ks = 0; ks < 4; ks++) {
            const int kbyte = ks * 32;
            uint32_t ah[4][4], al[4][4];
            #pragma unroll
            for (int mf = 0; mf < 4; mf++) {
                const uint32_t off = SW128((aRow + mf * 16) * 128 + kbyte + aKb);
                LDMX4(ah[mf][0], ah[mf][1], ah[mf][2], ah[mf][3],
                      stage + S_A_HI + off);
                LDMX4(al[mf][0], al[mf][1], al[mf][2], al[mf][3],
                      stage + S_A_LO + off);
            }
            #pragma unroll
            for (int np = 0; np < 4; np++) {
                const uint32_t off = SW128((bRowBase + np * 16) * 128 + kbyte + bKb);
                uint32_t h0, h1, h2r, h3, l0, l1, l2, l3;
                LDMX4(h0, h1, h2r, h3, stage + S_B_HI + off);
                LDMX4(l0, l1, l2, l3, stage + S_B_LO + off);
                #pragma unroll
                for (int mf = 0; mf < 4; mf++) {
                    MMA16816(acc[mf][2 * np],     ah[mf][0], ah[mf][1], ah[mf][2], ah[mf][3], h0, h1);
                    MMA16816(acc[mf][2 * np],     ah[mf][0], ah[mf][1], ah[mf][2], ah[mf][3], l0, l1);
                    MMA16816(acc[mf][2 * np],     al[mf][0], al[mf][1], al[mf][2], al[mf][3], h0, h1);
                    MMA16816(acc[mf][2 * np + 1], ah[mf][0], ah[mf][1], ah[mf][2], ah[mf][3], h2r, h3);
                    MMA16816(acc[mf][2 * np + 1], ah[mf][0], ah[mf][1], ah[mf][2], ah[mf][3], l2, l3);
                    MMA16816(acc[mf][2 * np + 1], al[mf][0], al[mf][1], al[mf][2], al[mf][3], h2r, h3);
                }
            }
        }
    }

    // ---- epilogue: bias + relu straight from registers ----
    #pragma unroll
    for (int mf = 0; mf < 4; mf++) {
        const int r0 = rowA0 + warpM * 64 + mf * 16 + g;
        const int r1 = r0 + 8;
        #pragma unroll
        for (int nf = 0; nf < 8; nf++) {
            const int col = colB0 + warpN * 64 + nf * 8 + tig * 2;
            const float bx = __ldg(bias + col);
            const float by = __ldg(bias + col + 1);
            float v0x = fmaxf(acc[mf][nf][0] + bx, 0.0f);
            float v0y = fmaxf(acc[mf][nf][1] + by, 0.0f);
            float v1x = fmaxf(acc[mf][nf][2] + bx, 0.0f);
            float v1y = fmaxf(acc[mf][nf][3] + by, 0.0f);
            if (mode) {
                __nv_bfloat162 h0, l0, h1, l1;
                h0.x = __float2bfloat16(v0x);
                h0.y = __float2bfloat16(v0y);
                l0.x = __float2bfloat16(v0x - __bfloat162float(h0.x));
                l0.y = __float2bfloat16(v0y - __bfloat162float(h0.y));
                h1.x = __float2bfloat16(v1x);
                h1.y = __float2bfloat16(v1y);
                l1.x = __float2bfloat16(v1x - __bfloat162float(h1.x));
                l1.y = __float2bfloat16(v1y - __bfloat162float(h1.y));
                *(__nv_bfloat162*)(outHi + (size_t)r0 * Npitch + col) = h0;
                *(__nv_bfloat162*)(outLo + (size_t)r0 * Npitch + col) = l0;
                *(__nv_bfloat162*)(outHi + (size_t)r1 * Npitch + col) = h1;
                *(__nv_bfloat162*)(outLo + (size_t)r1 * Npitch + col) = l1;
            } else {
                *(float2*)(outF + (size_t)r0 * Npitch + col) = make_float2(v0x, v0y);
                *(float2*)(outF + (size_t)r1 * Npitch + col) = make_float2(v1x, v1y);
            }
        }
    }
}

// ---------------------------------------------------------------------------
// GEMV: scores[r] = dot(H[r,:], w) + b
// ---------------------------------------------------------------------------
__global__ __launch_bounds__(256)
void gemv_scores(const float* __restrict__ H,
                 const float* __restrict__ w,
                 const float* __restrict__ b3,
                 float* __restrict__ scores,
                 int rows, int K)
{
    const int gwarp = (blockIdx.x * blockDim.x + threadIdx.x) >> 5;
    const int lane  = threadIdx.x & 31;
    if (gwarp >= rows) return;

    const float4* r4 = (const float4*)(H + (size_t)gwarp * K);
    const float4* w4 = (const float4*)w;
    const int K4 = K >> 2;

    float acc = 0.0f;
    for (int t = lane; t < K4; t += 32) {
        float4 a = r4[t];
        float4 b = w4[t];
        acc += a.x * b.x + a.y * b.y + a.z * b.z + a.w * b.w;
    }
    #pragma unroll
    for (int o = 16; o > 0; o >>= 1)
        acc += __shfl_down_sync(0xffffffffu, acc, o);
    if (lane == 0) scores[gwarp] = acc + b3[0];
}

// ---------------------------------------------------------------------------
// soft_rank (parallel PAV; contribution ~small)
// ---------------------------------------------------------------------------
__device__ __forceinline__ int pav_merge(int Lbase, int nl, int Rbase, int nr,
                                         int* __restrict__ pst,
                                         int* __restrict__ pcn,
                                         float* __restrict__ psm)
{
    int len = nl;
    for (int t = 0; t < nr; t++) {
        int   cs = pst[Rbase + t];
        int   cc = pcn[Rbase + t];
        float cm = psm[Rbase + t];
        while (len > 0) {
            float ts = psm[Lbase + len - 1];
            int   tc = pcn[Lbase + len - 1];
            if (ts * (float)cc < cm * (float)tc) {
                cm += ts; cc += tc; cs = pst[Lbase + len - 1];
                len--;
            } else break;
        }
        pst[Lbase + len] = cs;
        pcn[Lbase + len] = cc;
        psm[Lbase + len] = cm;
        len++;
    }
    return len;
}

__global__ void softrank_kernel(const float* __restrict__ scores,
                                float* __restrict__ out,
                                int n)
{
    extern __shared__ float smf[];
    float* s   = smf;
    float* psm = s + n;
    int*   idx = (int*)(psm + n);
    int*   pst = idx + n;
    int*   pcn = pst + n;
    int*   cA  = pcn + n;
    int*   cB  = cA + n / 2;

    const int tid = threadIdx.x;
    const int nt  = blockDim.x;

    for (int i = tid; i < n; i += nt) { s[i] = scores[i]; idx[i] = i; }
    __syncthreads();

    for (int k = 2; k <= n; k <<= 1) {
        for (int j = k >> 1; j > 0; j >>= 1) {
            for (int i = tid; i < n; i += nt) {
                int ixj = i ^ j;
                if (ixj > i) {
                    bool up = ((i & k) == 0);
                    float a = s[i], b = s[ixj];
                    bool sw = up ? (a < b) : (a > b);
                    if (sw) {
                        s[i] = b; s[ixj] = a;
                        int t = idx[i]; idx[i] = idx[ixj]; idx[ixj] = t;
                    }
                }
            }
            __syncthreads();
        }
    }

    for (int i = tid; i < n; i += nt) {
        pst[i] = i;
        pcn[i] = 1;
        psm[i] = s[i] - (float)(n - i);
    }
    __syncthreads();

    for (int g2 = tid; g2 < n / 2; g2 += nt)
        cA[g2] = pav_merge(2 * g2, 1, 2 * g2 + 1, 1, pst, pcn, psm);
    __syncthreads();

    int* cCur = cA;
    int* cNxt = cB;
    for (int L = 2; (1 << L) <= n; L++) {
        const int half = 1 << (L - 1);
        const int nm = n >> L;
        for (int g2 = tid; g2 < nm; g2 += nt)
            cNxt[g2] = pav_merge((g2 << L), cCur[2 * g2],
                                 (g2 << L) + half, cCur[2 * g2 + 1],
                                 pst, pcn, psm);
        __syncthreads();
        int* t = cCur; cCur = cNxt; cNxt = t;
    }
    const int P = cCur[0];

    for (int i = tid; i < n; i += nt) {
        int lo = 0, hi = P - 1;
        while (lo < hi) {
            int mid = (lo + hi + 1) >> 1;
            if (pst[mid] <= i) lo = mid; else hi = mid - 1;
        }
        float dual = psm[lo] / (float)pcn[lo];
        out[idx[i]] = s[i] - dual;
        out[n + i]  = scores[i];
    }
}

// ---------------------------------------------------------------------------
// Launch
// ---------------------------------------------------------------------------
extern "C" void kernel_launch(void* const* d_in, const int* in_sizes, int n_in,
                              void* d_out, int out_size)
{
    const float* x  = (const float*)d_in[0];
    const float* W1 = (const float*)d_in[1];
    const float* b1 = (const float*)d_in[2];
    const float* W2 = (const float*)d_in[3];
    const float* b2 = (const float*)d_in[4];
    const float* W3 = (const float*)d_in[5];
    const float* b3 = (const float*)d_in[6];
    float* out = (float*)d_out;

    __nv_bfloat16 *xhi, *xlo, *w1hi, *w1lo, *w2hi, *w2lo, *h1hi, *h1lo;
    float *h2, *sc;
    cudaGetSymbolAddress((void**)&xhi,  g_xhi);
    cudaGetSymbolAddress((void**)&xlo,  g_xlo);
    cudaGetSymbolAddress((void**)&w1hi, g_w1hi);
    cudaGetSymbolAddress((void**)&w1lo, g_w1lo);
    cudaGetSymbolAddress((void**)&w2hi, g_w2hi);
    cudaGetSymbolAddress((void**)&w2lo, g_w2lo);
    cudaGetSymbolAddress((void**)&h1hi, g_h1hi);
    cudaGetSymbolAddress((void**)&h1lo, g_h1lo);
    cudaGetSymbolAddress((void**)&h2,   g_h2);
    cudaGetSymbolAddress((void**)&sc,   g_scores);

    // conversions
    {
        int n = MB * DIN;
        split_rows<<<(n / 4 + 255) / 256, 256>>>(x, xhi, xlo, n);
        transpose_split<<<dim3(HID / 32, DIN / 32), dim3(32, 8)>>>(W1, w1hi, w1lo, DIN, HID);
        transpose_split<<<dim3(HID / 32, HID / 32), dim3(32, 8)>>>(W2, w2hi, w2lo, HID, HID);
    }

    cudaFuncSetAttribute(gemm_mma,
                         cudaFuncAttributeMaxDynamicSharedMemorySize, GEMM_SMEM);

    // layer 1: relu(x @ W1 + b1) -> h1 (split bf16)
    {
        dim3 grid(HID / BN, MB / BM);
        gemm_mma<<<grid, 256, GEMM_SMEM>>>(xhi, xlo, w1hi, w1lo, b1,
                                           DIN, HID, 1,
                                           nullptr, h1hi, h1lo);
    }
    // layer 2: relu(h1 @ W2 + b2) -> h2 (fp32)
    {
        dim3 grid(HID / BN, MB / BM);
        gemm_mma<<<grid, 256, GEMM_SMEM>>>(h1hi, h1lo, w2hi, w2lo, b2,
                                           HID, HID, 0,
                                           h2, nullptr, nullptr);
    }
    // layer 3: GEMV
    {
        int blocks = (MB + 7) / 8;
        gemv_scores<<<blocks, 256>>>(h2, W3, b3, sc, MB, HID);
    }
    // soft_rank (parallel PAV)
    {
        size_t smem = (size_t)MB * 6 * sizeof(float);
        cudaFuncSetAttribute(softrank_kernel,
                             cudaFuncAttributeMaxDynamicSharedMemorySize,
                             (int)smem);
        softrank_kernel<<<1, 1024, smem>>>(sc, out, MB);
    }
}